// round 11
// baseline (speedup 1.0000x reference)
#include <cuda_runtime.h>
#include <cuda_fp16.h>
#include <cstdint>

// Problem constants
#define IN_CH   4096
#define OUT_CH  4096
#define BATCH   8192

// GEMM tiling (fp16: 2 B/elem)
#define TM      256                  // batch rows per CTA tile
#define TN      128                  // out_ch cols per CTA tile
#define KC      64                   // K per chunk (64 fp16 = 128 B = swizzle row)
#define NCHUNK  (IN_CH / KC)         // 64
#define NSTAGE  4
#define NTHREADS 256                 // 8 warps, warp grid 4(m) x 2(n), warp tile 64x64

// smem: 4 stages of [A|B]
#define A_BYTES     (TM * 128)                     // 32768
#define B_BYTES     (TN * 128)                     // 16384
#define STAGE_BYTES (A_BYTES + B_BYTES)            // 49152
#define SMEM_TOTAL  (NSTAGE * STAGE_BYTES)         // 196608 (1 CTA/SM)

// Scratch (device globals: allocation-free per harness rules) — 96 MB
__device__ __half g_xh[(size_t)BATCH * IN_CH];    // fp16 x
__device__ __half g_wh[(size_t)OUT_CH * IN_CH];   // fp16 dense W

// ---------------------------------------------------------------------------
// PTX helpers (baseline sm_80+ instructions — valid on plain sm_103 target)
// ---------------------------------------------------------------------------
__device__ __forceinline__ uint32_t smem_u32(const void* p) {
    uint32_t a;
    asm("{ .reg .u64 t; cvta.to.shared.u64 t, %1; cvt.u32.u64 %0, t; }"
        : "=r"(a) : "l"(p));
    return a;
}
__device__ __forceinline__ void ldsm4(uint32_t* r, uint32_t addr) {
    asm volatile("ldmatrix.sync.aligned.m8n8.x4.shared.b16 {%0,%1,%2,%3}, [%4];"
                 : "=r"(r[0]), "=r"(r[1]), "=r"(r[2]), "=r"(r[3]) : "r"(addr));
}
__device__ __forceinline__ void mma_fp16(float* d, const uint32_t* a, const uint32_t* b) {
    asm volatile(
        "mma.sync.aligned.m16n8k16.row.col.f32.f16.f16.f32 "
        "{%0,%1,%2,%3}, {%4,%5,%6,%7}, {%8,%9}, {%0,%1,%2,%3};"
        : "+f"(d[0]), "+f"(d[1]), "+f"(d[2]), "+f"(d[3])
        : "r"(a[0]), "r"(a[1]), "r"(a[2]), "r"(a[3]), "r"(b[0]), "r"(b[1]));
}

// ---------------------------------------------------------------------------
// Prep kernels: fp32 -> fp16
// ---------------------------------------------------------------------------
__global__ void k_cvt_x(const float* __restrict__ x) {
    size_t i = ((size_t)blockIdx.x * 256 + threadIdx.x) * 4;
    float4 v = *reinterpret_cast<const float4*>(&x[i]);
    __half2* p = reinterpret_cast<__half2*>(&g_xh[i]);
    p[0] = __floats2half2_rn(v.x, v.y);
    p[1] = __floats2half2_rn(v.z, v.w);
}

__global__ void k_zero_w() {
    size_t i = ((size_t)blockIdx.x * 256 + threadIdx.x) * 8;   // 8 fp16 = 16 B
    *reinterpret_cast<uint4*>(&g_wh[i]) = make_uint4(0, 0, 0, 0);
}

__global__ void k_scatter_w(const float* __restrict__ w, const int* __restrict__ rows,
                            const int* __restrict__ cols, int nnz) {
    int i = blockIdx.x * 256 + threadIdx.x;
    if (i >= nnz) return;
    g_wh[(size_t)rows[i] * IN_CH + cols[i]] = __float2half_rn(w[i]);
}

// ---------------------------------------------------------------------------
// cp.async loader: one k-chunk (A 256x64 | B 128x64 fp16) into a stage.
// Row = 128 B; 16B segment s of row r stored at segment (s ^ (r & 7)).
// ---------------------------------------------------------------------------
__device__ __forceinline__ void load_chunk(uint32_t sbase, int chunk, int stage,
                                           int m0, int n0, int tid) {
    const int k0 = chunk * KC;
    const uint32_t stA = sbase + stage * STAGE_BYTES;
    const uint32_t stB = stA + A_BYTES;
#pragma unroll
    for (int it = 0; it < 3072 / NTHREADS; it++) {   // 12 iters of 16B
        int j = it * NTHREADS + tid;
        const __half* src;
        uint32_t dst;
        if (j < 2048) {                       // A: 256 rows x 8 segs
            int r = j >> 3, s = j & 7;
            src = g_xh + (size_t)(m0 + r) * IN_CH + k0 + s * 8;
            dst = stA + (uint32_t)(r * 128 + ((s ^ (r & 7)) * 16));
        } else {                              // B: 128 rows x 8 segs
            int jb = j - 2048;
            int r = jb >> 3, s = jb & 7;
            src = g_wh + (size_t)(n0 + r) * IN_CH + k0 + s * 8;
            dst = stB + (uint32_t)(r * 128 + ((s ^ (r & 7)) * 16));
        }
        asm volatile("cp.async.cg.shared.global [%0], [%1], 16;" :: "r"(dst), "l"(src));
    }
    asm volatile("cp.async.commit_group;" ::: "memory");
}

// ---------------------------------------------------------------------------
// Main GEMM: y[256 x 128] = x @ W^T + bias, single-pass fp16 mma.sync.
// 8 warps (4m x 2n), warp tile 64x64: 8 LDSM.x4 feed 32 MMAs per kt.
// ---------------------------------------------------------------------------
__global__ void __launch_bounds__(NTHREADS, 1)
k_gemm(const float* __restrict__ bias, float* __restrict__ y) {
    extern __shared__ char smem[];
    const uint32_t sbase = smem_u32(smem);
    const int tid  = threadIdx.x;
    const int warp = tid >> 5;
    const int lane = tid & 31;
    const int wm   = warp >> 1;           // 0..3  (m)
    const int wn   = warp & 1;            // 0..1  (n)
    const int n0   = blockIdx.x * TN;     // x fastest -> W tiles shared per wave
    const int m0   = blockIdx.y * TM;

    // ldmatrix per-thread offsets (layouts validated in R5/R8/R9).
    // A x4 tiles: groups -> (m0-7,k0),(m8-15,k0),(m0-7,k+8),(m8-15,k+8)
    const uint32_t amask = (uint32_t)(lane & 7) << 4;
    uint32_t arow[4];
#pragma unroll
    for (int mt = 0; mt < 4; mt++)
        arow[mt] = (uint32_t)((wm * 64 + mt * 16 + (lane & 15)) * 128
                              + ((lane >> 4) & 1) * 16);
    // B x4 tiles: groups -> (n0-7,k0),(n0-7,k+8),(n8-15,k0),(n8-15,k+8)
    uint32_t brow[4];
#pragma unroll
    for (int nt = 0; nt < 4; nt++)
        brow[nt] = (uint32_t)((wn * 64 + nt * 16 + (lane & 7) + ((lane >> 4) & 1) * 8) * 128
                              + ((lane >> 3) & 1) * 16);

    float acc[4][8][4];
#pragma unroll
    for (int mt = 0; mt < 4; mt++)
#pragma unroll
        for (int n8 = 0; n8 < 8; n8++)
#pragma unroll
            for (int q = 0; q < 4; q++) acc[mt][n8][q] = 0.0f;

    // Prologue: prefetch chunks 0..2 (stages 0..2)
    load_chunk(sbase, 0, 0, m0, n0, tid);
    load_chunk(sbase, 1, 1, m0, n0, tid);
    load_chunk(sbase, 2, 2, m0, n0, tid);

    for (int i = 0; i < NCHUNK; i++) {
        // Ensure chunk i's cp.async group has retired (groups retire in order)
        if (i < NCHUNK - 2)
            asm volatile("cp.async.wait_group 2;" ::: "memory");
        else if (i < NCHUNK - 1)
            asm volatile("cp.async.wait_group 1;" ::: "memory");
        else
            asm volatile("cp.async.wait_group 0;" ::: "memory");
        __syncthreads();   // chunk i visible; stage (i+3)%4's old chunk consumed

        if (i + 3 < NCHUNK)
            load_chunk(sbase, i + 3, (i + 3) % NSTAGE, m0, n0, tid);

        const uint32_t stA = sbase + (i % NSTAGE) * STAGE_BYTES;
        const uint32_t stB = stA + A_BYTES;

#pragma unroll
        for (int kt = 0; kt < 4; kt++) {       // 4 x k16 per 64-K chunk
            const uint32_t kb = (uint32_t)(kt * 32);   // 16 fp16 = 32 B
            uint32_t a[4][4], b[4][4];
#pragma unroll
            for (int mt = 0; mt < 4; mt++)
                ldsm4(a[mt], stA + ((arow[mt] + kb) ^ amask));
#pragma unroll
            for (int nt = 0; nt < 4; nt++)
                ldsm4(b[nt], stB + ((brow[nt] + kb) ^ amask));
#pragma unroll
            for (int mt = 0; mt < 4; mt++)
#pragma unroll
                for (int nt = 0; nt < 4; nt++) {
                    mma_fp16(acc[mt][nt * 2],     a[mt], &b[nt][0]);
                    mma_fp16(acc[mt][nt * 2 + 1], a[mt], &b[nt][2]);
                }
        }
    }

    // Epilogue: c0,c1=(m + l/4, n + 2(l%4)+{0,1}), c2,c3=(m+8, ...)
    const int mw = m0 + wm * 64 + (lane >> 2);
    const int nw = n0 + wn * 64 + 2 * (lane & 3);
#pragma unroll
    for (int mt = 0; mt < 4; mt++) {
        const size_t r0 = (size_t)(mw + mt * 16) * OUT_CH;
        const size_t r1 = r0 + 8 * OUT_CH;
#pragma unroll
        for (int n8 = 0; n8 < 8; n8++) {
            const int n = nw + n8 * 8;
            const float2 bv = *reinterpret_cast<const float2*>(&bias[n]);
            float2 v0, v1;
            v0.x = acc[mt][n8][0] + bv.x;  v0.y = acc[mt][n8][1] + bv.y;
            v1.x = acc[mt][n8][2] + bv.x;  v1.y = acc[mt][n8][3] + bv.y;
            *reinterpret_cast<float2*>(&y[r0 + n]) = v0;
            *reinterpret_cast<float2*>(&y[r1 + n]) = v1;
        }
    }
}

// ---------------------------------------------------------------------------
// Launch (graph-capturable: kernel launches only, default stream)
// ---------------------------------------------------------------------------
extern "C" void kernel_launch(void* const* d_in, const int* in_sizes, int n_in,
                              void* d_out, int out_size) {
    const float* x    = (const float*)d_in[0];
    const float* w    = (const float*)d_in[1];
    const int*   rows = (const int*)  d_in[2];
    const int*   cols = (const int*)  d_in[3];
    const float* bias = (const float*)d_in[4];
    float*       y    = (float*)d_out;
    const int    nnz  = in_sizes[1];

    cudaFuncSetAttribute(k_gemm, cudaFuncAttributeMaxDynamicSharedMemorySize,
                         SMEM_TOTAL);

    k_cvt_x<<<(BATCH * IN_CH / 4) / 256, 256>>>(x);
    k_zero_w<<<(int)(((size_t)OUT_CH * IN_CH / 8) / 256), 256>>>();
    k_scatter_w<<<(nnz + 255) / 256, 256>>>(w, rows, cols, nnz);
    k_gemm<<<dim3(OUT_CH / TN, BATCH / TM), NTHREADS, SMEM_TOTAL>>>(bias, y);
}

// round 12
// speedup vs baseline: 1.0813x; 1.0813x over previous
#include <cuda_runtime.h>
#include <cuda_fp16.h>
#include <cstdint>

// Problem constants
#define IN_CH   4096
#define OUT_CH  4096
#define BATCH   8192

// GEMM tiling (fp16: 2 B/elem) — R9 configuration (measured 576 us, 78.4% tensor)
#define TM      128                  // batch rows per CTA tile
#define TN      128                  // out_ch cols per CTA tile
#define KC      64                   // K per chunk (64 fp16 = 128 B = swizzle row)
#define NCHUNK  (IN_CH / KC)         // 64
#define NSTAGE  3
#define NTHREADS 128                 // 4 warps, warp grid 2(m) x 2(n), warp tile 64x64

// smem: 3 stages of [A|B]
#define A_BYTES     (TM * 128)                     // 16384
#define B_BYTES     (TN * 128)                     // 16384
#define STAGE_BYTES (A_BYTES + B_BYTES)            // 32768
#define SMEM_TOTAL  (NSTAGE * STAGE_BYTES)         // 98304 -> 2 CTAs/SM

// Scratch (device globals: allocation-free per harness rules) — 96 MB
__device__ __half g_xh[(size_t)BATCH * IN_CH];    // fp16 x
__device__ __half g_wh[(size_t)OUT_CH * IN_CH];   // fp16 dense W

// ---------------------------------------------------------------------------
// PTX helpers (baseline sm_80+ instructions — valid on plain sm_103 target)
// ---------------------------------------------------------------------------
__device__ __forceinline__ uint32_t smem_u32(const void* p) {
    uint32_t a;
    asm("{ .reg .u64 t; cvta.to.shared.u64 t, %1; cvt.u32.u64 %0, t; }"
        : "=r"(a) : "l"(p));
    return a;
}
__device__ __forceinline__ void ldsm4(uint32_t* r, uint32_t addr) {
    asm volatile("ldmatrix.sync.aligned.m8n8.x4.shared.b16 {%0,%1,%2,%3}, [%4];"
                 : "=r"(r[0]), "=r"(r[1]), "=r"(r[2]), "=r"(r[3]) : "r"(addr));
}
__device__ __forceinline__ void mma_fp16(float* d, const uint32_t* a, const uint32_t* b) {
    asm volatile(
        "mma.sync.aligned.m16n8k16.row.col.f32.f16.f16.f32 "
        "{%0,%1,%2,%3}, {%4,%5,%6,%7}, {%8,%9}, {%0,%1,%2,%3};"
        : "+f"(d[0]), "+f"(d[1]), "+f"(d[2]), "+f"(d[3])
        : "r"(a[0]), "r"(a[1]), "r"(a[2]), "r"(a[3]), "r"(b[0]), "r"(b[1]));
}

// ---------------------------------------------------------------------------
// Fused prep: x fp32->fp16 convert (blocks [0, XBLK)) and W zero
// (blocks [XBLK, XBLK+WBLK)). Independent ranges, one launch.
// ---------------------------------------------------------------------------
#define XBLK ((BATCH * IN_CH / 4) / 256)                       // 32768 blocks
#define WBLK ((int)(((size_t)OUT_CH * IN_CH / 16) / 256))      // 4096 blocks

__global__ void k_prep(const float* __restrict__ x) {
    const int b = blockIdx.x;
    if (b < XBLK) {
        size_t i = ((size_t)b * 256 + threadIdx.x) * 4;
        float4 v = *reinterpret_cast<const float4*>(&x[i]);
        __half2* p = reinterpret_cast<__half2*>(&g_xh[i]);
        p[0] = __floats2half2_rn(v.x, v.y);
        p[1] = __floats2half2_rn(v.z, v.w);
    } else {
        size_t i = ((size_t)(b - XBLK) * 256 + threadIdx.x) * 16;  // 16 fp16 = 32 B
        uint4 z = make_uint4(0, 0, 0, 0);
        *reinterpret_cast<uint4*>(&g_wh[i])     = z;
        *reinterpret_cast<uint4*>(&g_wh[i + 8]) = z;
    }
}

__global__ void k_scatter_w(const float* __restrict__ w, const int* __restrict__ rows,
                            const int* __restrict__ cols, int nnz) {
    int i = blockIdx.x * 256 + threadIdx.x;
    if (i >= nnz) return;
    g_wh[(size_t)rows[i] * IN_CH + cols[i]] = __float2half_rn(w[i]);
}

// ---------------------------------------------------------------------------
// cp.async loader: one k-chunk (A 128x64 | B 128x64 fp16) into a stage.
// Row = 128 B; 16B segment s of row r stored at segment (s ^ (r & 7)).
// ---------------------------------------------------------------------------
__device__ __forceinline__ void load_chunk(uint32_t sbase, int chunk, int stage,
                                           int m0, int n0, int tid) {
    const int k0 = chunk * KC;
    const uint32_t stA = sbase + stage * STAGE_BYTES;
    const uint32_t stB = stA + A_BYTES;
#pragma unroll
    for (int it = 0; it < 2048 / NTHREADS; it++) {   // 16 iters of 16B
        int j = it * NTHREADS + tid;
        const __half* src;
        uint32_t dst;
        if (j < 1024) {                       // A: 128 rows x 8 segs
            int r = j >> 3, s = j & 7;
            src = g_xh + (size_t)(m0 + r) * IN_CH + k0 + s * 8;
            dst = stA + (uint32_t)(r * 128 + ((s ^ (r & 7)) * 16));
        } else {                              // B: 128 rows x 8 segs
            int jb = j - 1024;
            int r = jb >> 3, s = jb & 7;
            src = g_wh + (size_t)(n0 + r) * IN_CH + k0 + s * 8;
            dst = stB + (uint32_t)(r * 128 + ((s ^ (r & 7)) * 16));
        }
        asm volatile("cp.async.cg.shared.global [%0], [%1], 16;" :: "r"(dst), "l"(src));
    }
    asm volatile("cp.async.commit_group;" ::: "memory");
}

// ---------------------------------------------------------------------------
// Main GEMM (R9 verbatim): y[128 x 128] = x @ W^T + bias, fp16 mma.sync.
// 4 warps, warp tile 64x64: 8 LDSM.x4 feed 32 MMAs per kt (128 B/MMA).
// ---------------------------------------------------------------------------
__global__ void __launch_bounds__(NTHREADS, 2)
k_gemm(const float* __restrict__ bias, float* __restrict__ y) {
    extern __shared__ char smem[];
    const uint32_t sbase = smem_u32(smem);
    const int tid  = threadIdx.x;
    const int warp = tid >> 5;
    const int lane = tid & 31;
    const int wm   = warp >> 1;           // 0..1  (m)
    const int wn   = warp & 1;            // 0..1  (n)
    const int n0   = blockIdx.x * TN;     // x fastest -> W tiles shared per wave
    const int m0   = blockIdx.y * TM;

    // ldmatrix per-thread offsets (layouts validated in R5/R8/R9).
    const uint32_t amask = (uint32_t)(lane & 7) << 4;
    uint32_t arow[4];
#pragma unroll
    for (int mt = 0; mt < 4; mt++)
        arow[mt] = (uint32_t)((wm * 64 + mt * 16 + (lane & 15)) * 128
                              + ((lane >> 4) & 1) * 16);
    uint32_t brow[4];
#pragma unroll
    for (int nt = 0; nt < 4; nt++)
        brow[nt] = (uint32_t)((wn * 64 + nt * 16 + (lane & 7) + ((lane >> 4) & 1) * 8) * 128
                              + ((lane >> 3) & 1) * 16);

    float acc[4][8][4];
#pragma unroll
    for (int mt = 0; mt < 4; mt++)
#pragma unroll
        for (int n8 = 0; n8 < 8; n8++)
#pragma unroll
            for (int q = 0; q < 4; q++) acc[mt][n8][q] = 0.0f;

    // Prologue: prefetch chunks 0, 1 (stages 0, 1)
    load_chunk(sbase, 0, 0, m0, n0, tid);
    load_chunk(sbase, 1, 1, m0, n0, tid);

    for (int i = 0; i < NCHUNK; i++) {
        if (i < NCHUNK - 1)
            asm volatile("cp.async.wait_group 1;" ::: "memory");
        else
            asm volatile("cp.async.wait_group 0;" ::: "memory");
        __syncthreads();   // chunk i visible; stage (i+2)%3's old chunk consumed

        if (i + 2 < NCHUNK)
            load_chunk(sbase, i + 2, (i + 2) % NSTAGE, m0, n0, tid);

        const uint32_t stA = sbase + (i % NSTAGE) * STAGE_BYTES;
        const uint32_t stB = stA + A_BYTES;

#pragma unroll
        for (int kt = 0; kt < 4; kt++) {       // 4 x k16 per 64-K chunk
            const uint32_t kb = (uint32_t)(kt * 32);   // 16 fp16 = 32 B
            uint32_t a[4][4], b[4][4];
#pragma unroll
            for (int mt = 0; mt < 4; mt++)
                ldsm4(a[mt], stA + ((arow[mt] + kb) ^ amask));
#pragma unroll
            for (int nt = 0; nt < 4; nt++)
                ldsm4(b[nt], stB + ((brow[nt] + kb) ^ amask));
#pragma unroll
            for (int mt = 0; mt < 4; mt++)
#pragma unroll
                for (int nt = 0; nt < 4; nt++) {
                    mma_fp16(acc[mt][nt * 2],     a[mt], &b[nt][0]);
                    mma_fp16(acc[mt][nt * 2 + 1], a[mt], &b[nt][2]);
                }
        }
    }

    // Epilogue: c0,c1=(m + l/4, n + 2(l%4)+{0,1}), c2,c3=(m+8, ...)
    const int mw = m0 + wm * 64 + (lane >> 2);
    const int nw = n0 + wn * 64 + 2 * (lane & 3);
#pragma unroll
    for (int mt = 0; mt < 4; mt++) {
        const size_t r0 = (size_t)(mw + mt * 16) * OUT_CH;
        const size_t r1 = r0 + 8 * OUT_CH;
#pragma unroll
        for (int n8 = 0; n8 < 8; n8++) {
            const int n = nw + n8 * 8;
            const float2 bv = *reinterpret_cast<const float2*>(&bias[n]);
            float2 v0, v1;
            v0.x = acc[mt][n8][0] + bv.x;  v0.y = acc[mt][n8][1] + bv.y;
            v1.x = acc[mt][n8][2] + bv.x;  v1.y = acc[mt][n8][3] + bv.y;
            *reinterpret_cast<float2*>(&y[r0 + n]) = v0;
            *reinterpret_cast<float2*>(&y[r1 + n]) = v1;
        }
    }
}

// ---------------------------------------------------------------------------
// Launch (graph-capturable: kernel launches only, default stream)
// ---------------------------------------------------------------------------
extern "C" void kernel_launch(void* const* d_in, const int* in_sizes, int n_in,
                              void* d_out, int out_size) {
    const float* x    = (const float*)d_in[0];
    const float* w    = (const float*)d_in[1];
    const int*   rows = (const int*)  d_in[2];
    const int*   cols = (const int*)  d_in[3];
    const float* bias = (const float*)d_in[4];
    float*       y    = (float*)d_out;
    const int    nnz  = in_sizes[1];

    cudaFuncSetAttribute(k_gemm, cudaFuncAttributeMaxDynamicSharedMemorySize,
                         SMEM_TOTAL);

    k_prep<<<XBLK + WBLK, 256>>>(x);
    k_scatter_w<<<(nnz + 255) / 256, 256>>>(w, rows, cols, nnz);
    k_gemm<<<dim3(OUT_CH / TN, BATCH / TM), NTHREADS, SMEM_TOTAL>>>(bias, y);
}

// round 13
// speedup vs baseline: 1.0829x; 1.0015x over previous
#include <cuda_runtime.h>
#include <cuda_fp16.h>
#include <cstdint>

// Problem constants
#define IN_CH   4096
#define OUT_CH  4096
#define BATCH   8192

// GEMM tiling (fp16: 2 B/elem) — R9 configuration (measured 576 us, 78.4% tensor)
#define TM      128                  // batch rows per CTA tile
#define TN      128                  // out_ch cols per CTA tile
#define KC      64                   // K per chunk (64 fp16 = 128 B = swizzle row)
#define NCHUNK  (IN_CH / KC)         // 64
#define NSTAGE  3
#define NTHREADS 128                 // 4 warps, warp grid 2(m) x 2(n), warp tile 64x64

// smem: 3 stages of [A|B]
#define A_BYTES     (TM * 128)                     // 16384
#define B_BYTES     (TN * 128)                     // 16384
#define STAGE_BYTES (A_BYTES + B_BYTES)            // 32768
#define SMEM_TOTAL  (NSTAGE * STAGE_BYTES)         // 98304 -> 2 CTAs/SM

// Scratch (device globals: allocation-free per harness rules) — 96 MB
__device__ __half g_xh[(size_t)BATCH * IN_CH];    // fp16 x
__device__ __half g_wh[(size_t)OUT_CH * IN_CH];   // fp16 dense W

// ---------------------------------------------------------------------------
// PTX helpers (baseline sm_80+ instructions — valid on plain sm_103 target)
// ---------------------------------------------------------------------------
__device__ __forceinline__ uint32_t smem_u32(const void* p) {
    uint32_t a;
    asm("{ .reg .u64 t; cvta.to.shared.u64 t, %1; cvt.u32.u64 %0, t; }"
        : "=r"(a) : "l"(p));
    return a;
}
__device__ __forceinline__ void ldsm4(uint32_t* r, uint32_t addr) {
    asm volatile("ldmatrix.sync.aligned.m8n8.x4.shared.b16 {%0,%1,%2,%3}, [%4];"
                 : "=r"(r[0]), "=r"(r[1]), "=r"(r[2]), "=r"(r[3]) : "r"(addr));
}
__device__ __forceinline__ void mma_fp16(float* d, const uint32_t* a, const uint32_t* b) {
    asm volatile(
        "mma.sync.aligned.m16n8k16.row.col.f32.f16.f16.f32 "
        "{%0,%1,%2,%3}, {%4,%5,%6,%7}, {%8,%9}, {%0,%1,%2,%3};"
        : "+f"(d[0]), "+f"(d[1]), "+f"(d[2]), "+f"(d[3])
        : "r"(a[0]), "r"(a[1]), "r"(a[2]), "r"(a[3]), "r"(b[0]), "r"(b[1]));
}

// ---------------------------------------------------------------------------
// Prep kernels, ordered for minimal serial chain:
//   k_zero_w (4 us) -> k_scatter_w (8 us) -> k_cvt_x (~25 us) -> k_gemm
// (scatter only depends on zero; the long cvt no longer blocks it)
// ---------------------------------------------------------------------------
__global__ void k_zero_w() {
    size_t i = ((size_t)blockIdx.x * 256 + threadIdx.x) * 16;   // 16 fp16 = 32 B
    uint4 z = make_uint4(0, 0, 0, 0);
    *reinterpret_cast<uint4*>(&g_wh[i])     = z;
    *reinterpret_cast<uint4*>(&g_wh[i + 8]) = z;
}

__global__ void k_scatter_w(const float* __restrict__ w, const int* __restrict__ rows,
                            const int* __restrict__ cols, int nnz) {
    int i = blockIdx.x * 256 + threadIdx.x;
    if (i >= nnz) return;
    g_wh[(size_t)rows[i] * IN_CH + cols[i]] = __float2half_rn(w[i]);
}

__global__ void k_cvt_x(const float* __restrict__ x) {
    // 8 floats per thread: two independent float4 loads (MLP=2), one 16B store
    size_t i = ((size_t)blockIdx.x * 256 + threadIdx.x) * 8;
    float4 v0 = *reinterpret_cast<const float4*>(&x[i]);
    float4 v1 = *reinterpret_cast<const float4*>(&x[i + 4]);
    __half2 h[4];
    h[0] = __floats2half2_rn(v0.x, v0.y);
    h[1] = __floats2half2_rn(v0.z, v0.w);
    h[2] = __floats2half2_rn(v1.x, v1.y);
    h[3] = __floats2half2_rn(v1.z, v1.w);
    *reinterpret_cast<uint4*>(&g_xh[i]) = *reinterpret_cast<uint4*>(h);
}

// ---------------------------------------------------------------------------
// cp.async loader: one k-chunk (A 128x64 | B 128x64 fp16) into a stage.
// Row = 128 B; 16B segment s of row r stored at segment (s ^ (r & 7)).
// ---------------------------------------------------------------------------
__device__ __forceinline__ void load_chunk(uint32_t sbase, int chunk, int stage,
                                           int m0, int n0, int tid) {
    const int k0 = chunk * KC;
    const uint32_t stA = sbase + stage * STAGE_BYTES;
    const uint32_t stB = stA + A_BYTES;
#pragma unroll
    for (int it = 0; it < 2048 / NTHREADS; it++) {   // 16 iters of 16B
        int j = it * NTHREADS + tid;
        const __half* src;
        uint32_t dst;
        if (j < 1024) {                       // A: 128 rows x 8 segs
            int r = j >> 3, s = j & 7;
            src = g_xh + (size_t)(m0 + r) * IN_CH + k0 + s * 8;
            dst = stA + (uint32_t)(r * 128 + ((s ^ (r & 7)) * 16));
        } else {                              // B: 128 rows x 8 segs
            int jb = j - 1024;
            int r = jb >> 3, s = jb & 7;
            src = g_wh + (size_t)(n0 + r) * IN_CH + k0 + s * 8;
            dst = stB + (uint32_t)(r * 128 + ((s ^ (r & 7)) * 16));
        }
        asm volatile("cp.async.cg.shared.global [%0], [%1], 16;" :: "r"(dst), "l"(src));
    }
    asm volatile("cp.async.commit_group;" ::: "memory");
}

// ---------------------------------------------------------------------------
// Main GEMM (R9 verbatim): y[128 x 128] = x @ W^T + bias, fp16 mma.sync.
// 4 warps, warp tile 64x64: 8 LDSM.x4 feed 32 MMAs per kt (128 B/MMA).
// ---------------------------------------------------------------------------
__global__ void __launch_bounds__(NTHREADS, 2)
k_gemm(const float* __restrict__ bias, float* __restrict__ y) {
    extern __shared__ char smem[];
    const uint32_t sbase = smem_u32(smem);
    const int tid  = threadIdx.x;
    const int warp = tid >> 5;
    const int lane = tid & 31;
    const int wm   = warp >> 1;           // 0..1  (m)
    const int wn   = warp & 1;            // 0..1  (n)
    const int n0   = blockIdx.x * TN;     // x fastest -> W tiles shared per wave
    const int m0   = blockIdx.y * TM;

    // ldmatrix per-thread offsets (layouts validated in R5/R8/R9).
    const uint32_t amask = (uint32_t)(lane & 7) << 4;
    uint32_t arow[4];
#pragma unroll
    for (int mt = 0; mt < 4; mt++)
        arow[mt] = (uint32_t)((wm * 64 + mt * 16 + (lane & 15)) * 128
                              + ((lane >> 4) & 1) * 16);
    uint32_t brow[4];
#pragma unroll
    for (int nt = 0; nt < 4; nt++)
        brow[nt] = (uint32_t)((wn * 64 + nt * 16 + (lane & 7) + ((lane >> 4) & 1) * 8) * 128
                              + ((lane >> 3) & 1) * 16);

    float acc[4][8][4];
#pragma unroll
    for (int mt = 0; mt < 4; mt++)
#pragma unroll
        for (int n8 = 0; n8 < 8; n8++)
#pragma unroll
            for (int q = 0; q < 4; q++) acc[mt][n8][q] = 0.0f;

    // Prologue: prefetch chunks 0, 1 (stages 0, 1)
    load_chunk(sbase, 0, 0, m0, n0, tid);
    load_chunk(sbase, 1, 1, m0, n0, tid);

    for (int i = 0; i < NCHUNK; i++) {
        if (i < NCHUNK - 1)
            asm volatile("cp.async.wait_group 1;" ::: "memory");
        else
            asm volatile("cp.async.wait_group 0;" ::: "memory");
        __syncthreads();   // chunk i visible; stage (i+2)%3's old chunk consumed

        if (i + 2 < NCHUNK)
            load_chunk(sbase, i + 2, (i + 2) % NSTAGE, m0, n0, tid);

        const uint32_t stA = sbase + (i % NSTAGE) * STAGE_BYTES;
        const uint32_t stB = stA + A_BYTES;

#pragma unroll
        for (int kt = 0; kt < 4; kt++) {       // 4 x k16 per 64-K chunk
            const uint32_t kb = (uint32_t)(kt * 32);   // 16 fp16 = 32 B
            uint32_t a[4][4], b[4][4];
#pragma unroll
            for (int mt = 0; mt < 4; mt++)
                ldsm4(a[mt], stA + ((arow[mt] + kb) ^ amask));
#pragma unroll
            for (int nt = 0; nt < 4; nt++)
                ldsm4(b[nt], stB + ((brow[nt] + kb) ^ amask));
#pragma unroll
            for (int mt = 0; mt < 4; mt++)
#pragma unroll
                for (int nt = 0; nt < 4; nt++) {
                    mma_fp16(acc[mt][nt * 2],     a[mt], &b[nt][0]);
                    mma_fp16(acc[mt][nt * 2 + 1], a[mt], &b[nt][2]);
                }
        }
    }

    // Epilogue: c0,c1=(m + l/4, n + 2(l%4)+{0,1}), c2,c3=(m+8, ...)
    const int mw = m0 + wm * 64 + (lane >> 2);
    const int nw = n0 + wn * 64 + 2 * (lane & 3);
#pragma unroll
    for (int mt = 0; mt < 4; mt++) {
        const size_t r0 = (size_t)(mw + mt * 16) * OUT_CH;
        const size_t r1 = r0 + 8 * OUT_CH;
#pragma unroll
        for (int n8 = 0; n8 < 8; n8++) {
            const int n = nw + n8 * 8;
            const float2 bv = *reinterpret_cast<const float2*>(&bias[n]);
            float2 v0, v1;
            v0.x = acc[mt][n8][0] + bv.x;  v0.y = acc[mt][n8][1] + bv.y;
            v1.x = acc[mt][n8][2] + bv.x;  v1.y = acc[mt][n8][3] + bv.y;
            *reinterpret_cast<float2*>(&y[r0 + n]) = v0;
            *reinterpret_cast<float2*>(&y[r1 + n]) = v1;
        }
    }
}

// ---------------------------------------------------------------------------
// Launch (graph-capturable: kernel launches only, default stream)
// ---------------------------------------------------------------------------
extern "C" void kernel_launch(void* const* d_in, const int* in_sizes, int n_in,
                              void* d_out, int out_size) {
    const float* x    = (const float*)d_in[0];
    const float* w    = (const float*)d_in[1];
    const int*   rows = (const int*)  d_in[2];
    const int*   cols = (const int*)  d_in[3];
    const float* bias = (const float*)d_in[4];
    float*       y    = (float*)d_out;
    const int    nnz  = in_sizes[1];

    cudaFuncSetAttribute(k_gemm, cudaFuncAttributeMaxDynamicSharedMemorySize,
                         SMEM_TOTAL);

    // Short dependency first: zero -> scatter, then the long cvt, then GEMM.
    k_zero_w<<<(int)(((size_t)OUT_CH * IN_CH / 16) / 256), 256>>>();
    k_scatter_w<<<(nnz + 255) / 256, 256>>>(w, rows, cols, nnz);
    k_cvt_x<<<(BATCH * IN_CH / 8) / 256, 256>>>(x);
    k_gemm<<<dim3(OUT_CH / TN, BATCH / TM), NTHREADS, SMEM_TOTAL>>>(bias, y);
}